// round 3
// baseline (speedup 1.0000x reference)
#include <cuda_runtime.h>
#include <cstdint>

// DepConv3D: depth-gated 3x3 conv. Per tap, exactly one of slice0 (dn==dc-1)
// or slice1 (dn==dc) can be active (mutually exclusive), so we SELECT the
// weight line address per (pixel, tap) instead of computing both masked
// products -> halves the FFMA2 count vs the 515us kernel. Weight layout is
// slice-interleaved (16B lines at j*32 + slice*16) so per-lane slice-divergent
// LDS.128 hits adjacent bank-quads. All 16 feature channels staged in dynamic
// smem up front: one sync, then a pure LDS+FFMA2 loop.
// R2 fix: FT_WP=36 (even) so float2 reads from sF are 8B-aligned.

#define BB 4
#define CC 16
#define HH 512
#define WW 512
#define OCC 32
#define TILE_H 16
#define TILE_W 32
#define FT_H 18
#define FT_W 34
#define FT_WP 36   // EVEN row stride: float2-aligned; halves' spans contiguous

#define SW_BYTES (9*16*8*2*16)          // [k][i][j][slice] 16B lines = 36864 B
#define SF_FLOATS (CC*FT_H*FT_WP)       // 10368
#define SF_BYTES (SF_FLOATS*4)          // 41472 B
#define SD_INTS (FT_H*FT_W)             // 612
#define SMEM_TOTAL (SW_BYTES + SF_BYTES + SD_INTS*4)   // 80784 B

__global__ __launch_bounds__(256, 2)
void depconv3d_kernel(const float* __restrict__ feat,
                      const int*   __restrict__ depth,
                      const float* __restrict__ wgt,
                      float* __restrict__ out)
{
    extern __shared__ char smem[];
    float* sW = (float*)smem;                       // packed weights
    float* sF = (float*)(smem + SW_BYTES);          // [i][18][36]
    int*   sD = (int*)(smem + SW_BYTES + SF_BYTES); // [18][34]

    const int tx = threadIdx.x;     // 0..15
    const int ty = threadIdx.y;     // 0..15
    const int tid = ty * 16 + tx;
    const int b  = blockIdx.z;
    const int y0 = blockIdx.y * TILE_H;
    const int x0 = blockIdx.x * TILE_W;

    // ---- coalesced weight load, scatter into packed layout (skip dead slice 2)
    // dest float idx = (k*16+i)*64 + j*8 + d*4 + (o&3),  j = o>>2
    for (int idx = tid; idx < 32 * 16 * 27; idx += 256) {
        float w = wgt[idx];
        int k = idx % 9;
        int d = (idx / 9) % 3;
        int i = (idx / 27) % 16;
        int o = idx / (27 * 16);
        if (d < 2)
            sW[(k * 16 + i) * 64 + (o >> 2) * 8 + d * 4 + (o & 3)] = w;
    }

    // ---- depth tile (zero-padded; padded features are 0 so mask there is moot)
    for (int idx = tid; idx < FT_H * FT_W; idx += 256) {
        int r = idx / FT_W, c = idx - r * FT_W;
        int gy = y0 + r - 1, gx = x0 + c - 1;
        int d = 0;
        if (gy >= 0 && gy < HH && gx >= 0 && gx < WW)
            d = depth[(b * HH + gy) * WW + gx];
        sD[idx] = d;
    }
    __syncthreads();

    // ---- per-pixel masks: fm = tap active, sel = use slice1 (dn==dc)
    const int lx = tx * 2;
    unsigned fm0 = 0, fm1 = 0, sel0 = 0, sel1 = 0;
    {
        int dc0 = sD[(ty + 1) * FT_W + lx + 1];
        int dc1 = sD[(ty + 1) * FT_W + lx + 2];
        #pragma unroll
        for (int k = 0; k < 9; k++) {
            int ky = k / 3, kx = k - ky * 3;
            int dn0 = sD[(ty + ky) * FT_W + lx + kx];
            int dn1 = sD[(ty + ky) * FT_W + lx + kx + 1];
            unsigned A0 = (dn0 == dc0 - 1), B0 = (dn0 == dc0);
            unsigned A1 = (dn1 == dc1 - 1), B1 = (dn1 == dc1);
            fm0 |= (A0 | B0) << k;  sel0 |= B0 << k;
            fm1 |= (A1 | B1) << k;  sel1 |= B1 << k;
        }
    }

    // ---- stage ALL feature channels
    for (int idx = tid; idx < SF_FLOATS; idx += 256) {
        int c   = idx % FT_WP;
        int rem = idx / FT_WP;
        int r   = rem % FT_H;
        int i   = rem / FT_H;
        float v = 0.f;
        if (c < FT_W) {
            int gy = y0 + r - 1, gx = x0 + c - 1;
            if (gy >= 0 && gy < HH && gx >= 0 && gx < WW)
                v = feat[((size_t)(b * CC + i) * HH + gy) * WW + gx];
        }
        sF[idx] = v;
    }
    __syncthreads();

    unsigned long long acc0[16], acc1[16];
    #pragma unroll
    for (int p = 0; p < 16; p++) { acc0[p] = 0ull; acc1[p] = 0ull; }

    const unsigned wb = (unsigned)__cvta_generic_to_shared(sW);

    #pragma unroll 1
    for (int i = 0; i < CC; i++) {
        // 3x4 feature footprint for this thread's 2 pixels, once per channel
        float fr[12];
        #pragma unroll
        for (int r = 0; r < 3; r++) {
            const float* p = sF + (i * FT_H + ty + r) * FT_WP + lx;
            float2 u0 = *(const float2*)p;
            float2 u1 = *(const float2*)(p + 2);
            fr[r * 4 + 0] = u0.x; fr[r * 4 + 1] = u0.y;
            fr[r * 4 + 2] = u1.x; fr[r * 4 + 3] = u1.y;
        }
        const unsigned basei = wb + (unsigned)i * 256u;

        #pragma unroll
        for (int k = 0; k < 9; k++) {
            const int ky = k / 3, kx = k - ky * 3;
            float f0 = ((fm0 >> k) & 1) ? fr[ky * 4 + kx]     : 0.f;
            float f1 = ((fm1 >> k) & 1) ? fr[ky * 4 + kx + 1] : 0.f;
            unsigned long long F0, F1;
            asm("mov.b64 %0,{%1,%1};" : "=l"(F0) : "r"(__float_as_uint(f0)));
            asm("mov.b64 %0,{%1,%1};" : "=l"(F1) : "r"(__float_as_uint(f1)));
            unsigned a0 = basei + (unsigned)(k * 4096) + (((sel0 >> k) & 1u) << 4);
            unsigned a1 = basei + (unsigned)(k * 4096) + (((sel1 >> k) & 1u) << 4);
            #pragma unroll
            for (int j = 0; j < 8; j++) {
                unsigned long long w0, w1;
                asm("ld.shared.v2.b64 {%0,%1},[%2];"
                    : "=l"(w0), "=l"(w1) : "r"(a0 + j * 32));
                asm("fma.rn.f32x2 %0,%1,%2,%0;" : "+l"(acc0[2*j])   : "l"(F0), "l"(w0));
                asm("fma.rn.f32x2 %0,%1,%2,%0;" : "+l"(acc0[2*j+1]) : "l"(F0), "l"(w1));
                asm("ld.shared.v2.b64 {%0,%1},[%2];"
                    : "=l"(w0), "=l"(w1) : "r"(a1 + j * 32));
                asm("fma.rn.f32x2 %0,%1,%2,%0;" : "+l"(acc1[2*j])   : "l"(F1), "l"(w0));
                asm("fma.rn.f32x2 %0,%1,%2,%0;" : "+l"(acc1[2*j+1]) : "l"(F1), "l"(w1));
            }
        }
    }

    // ---- epilogue: acc[p] holds channels (2p, 2p+1) for each pixel
    const int gx = x0 + lx;
    const int gy = y0 + ty;
    #pragma unroll
    for (int p = 0; p < 16; p++) {
        float2 p0 = *reinterpret_cast<float2*>(&acc0[p]);
        float2 p1 = *reinterpret_cast<float2*>(&acc1[p]);
        size_t base = (((size_t)(b * OCC + 2 * p) * HH + gy) * WW) + gx;
        *reinterpret_cast<float2*>(out + base)                   = make_float2(p0.x, p1.x);
        *reinterpret_cast<float2*>(out + base + (size_t)HH * WW) = make_float2(p0.y, p1.y);
    }
}

extern "C" void kernel_launch(void* const* d_in, const int* in_sizes, int n_in,
                              void* d_out, int out_size)
{
    const float* feat  = (const float*)d_in[0];
    const int*   depth = (const int*)d_in[1];
    const float* wgt   = (const float*)d_in[2];
    float* out = (float*)d_out;

    cudaFuncSetAttribute(depconv3d_kernel,
                         cudaFuncAttributeMaxDynamicSharedMemorySize, SMEM_TOTAL);

    dim3 block(16, 16);
    dim3 grid(WW / TILE_W, HH / TILE_H, BB);
    depconv3d_kernel<<<grid, block, SMEM_TOTAL>>>(feat, depth, wgt, out);
}